// round 6
// baseline (speedup 1.0000x reference)
#include <cuda_runtime.h>
#include <cuda_bf16.h>

#define BB   4096      // batch rows
#define SEQ  2048      // sequence length S
#define SU   2056      // u row stride (S + E)
#define OUTW 2057      // out row stride (S + AR + 1)
#define KC   64        // chunk length
#define NCH  32        // chunks per row (SEQ / KC)
#define ORD  9         // recurrence order (AR + 1)
#define EX   8         // exogenous dim
#define BT   128       // b-rows per block in the two big passes

typedef unsigned long long u64;

// Static device scratch (b-fastest layouts)
__device__ float g_v[NCH * ORD * BB];      // [m][k][b] zero-state final windows
__device__ float g_s[NCH * ORD * BB];      // [m][k][b] true boundary states

// ---- packed f32x2 helpers -------------------------------------------------
__device__ __forceinline__ u64 pk2(float lo, float hi) {
    u64 r; asm("mov.b64 %0, {%1, %2};" : "=l"(r) : "f"(lo), "f"(hi)); return r;
}
__device__ __forceinline__ void upk2(u64 v, float& lo, float& hi) {
    asm("mov.b64 {%0, %1}, %2;" : "=f"(lo), "=f"(hi) : "l"(v));
}
__device__ __forceinline__ u64 f2fma(u64 a, u64 b, u64 c) {
    u64 d; asm("fma.rn.f32x2 %0, %1, %2, %3;" : "=l"(d) : "l"(a), "l"(b), "l"(c)); return d;
}
__device__ __forceinline__ u64 f2mul(u64 a, u64 b) {
    u64 d; asm("mul.rn.f32x2 %0, %1, %2;" : "=l"(d) : "l"(a), "l"(b)); return d;
}
__device__ __forceinline__ u64 f2add(u64 a, u64 b) {
    u64 d; asm("add.rn.f32x2 %0, %1, %2;" : "=l"(d) : "l"(a), "l"(b)); return d;
}

// load a-coefs (scalar) from W
__device__ __forceinline__ void load_a(const float* __restrict__ W, float* a) {
    a[0] = -__ldg(&W[0]);
    #pragma unroll
    for (int k = 1; k < 8; k++) a[k] = __ldg(&W[k - 1]) - __ldg(&W[k]);
    a[8] = 1.0f + __ldg(&W[7]);
}

// One packed recurrence step: returns new x (2 rows). c from uw, state from w.
__device__ __forceinline__ u64 step_packed(const u64* a2, const u64* wu2,
                                           const u64* uw, const u64* w, int j) {
    u64 q0 = f2mul(wu2[0], uw[(0 + j) % 9]);
    u64 q1 = f2mul(wu2[2], uw[(2 + j) % 9]);
    u64 q2 = f2mul(wu2[4], uw[(4 + j) % 9]);
    u64 q3 = f2mul(wu2[6], uw[(6 + j) % 9]);
    q0 = f2fma(wu2[1], uw[(1 + j) % 9], q0);
    q1 = f2fma(wu2[3], uw[(3 + j) % 9], q1);
    q2 = f2fma(wu2[5], uw[(5 + j) % 9], q2);
    q3 = f2fma(wu2[7], uw[(7 + j) % 9], q3);
    u64 c = f2add(f2add(q0, q1), f2add(q2, q3));

    u64 c0 = f2fma(a2[0], w[(0 + j) % 9], c);
    u64 c1 = f2mul(a2[1], w[(1 + j) % 9]);
    u64 c2 = f2mul(a2[2], w[(2 + j) % 9]);
    u64 c3 = f2mul(a2[3], w[(3 + j) % 9]);
    c0 = f2fma(a2[4], w[(4 + j) % 9], c0);
    c1 = f2fma(a2[5], w[(5 + j) % 9], c1);
    c2 = f2fma(a2[6], w[(6 + j) % 9], c2);
    c3 = f2fma(a2[7], w[(7 + j) % 9], c3);
    u64 x = f2add(f2add(c0, c1), f2add(c2, c3));
    return f2fma(a2[8], w[(8 + j) % 9], x);     // prev-x dependency: 4-cyc chain
}

__device__ __forceinline__ void load_coefs_packed(const float* __restrict__ W,
                                                  u64* a2, u64* wu2) {
    float a[ORD];
    load_a(W, a);
    #pragma unroll
    for (int k = 0; k < ORD; k++) a2[k] = pk2(a[k], a[k]);
    #pragma unroll
    for (int e = 0; e < EX; e++) { float v = __ldg(&W[8 + e]); wu2[e] = pk2(v, v); }
}

// ---------------------------------------------------------------------------
// Kernel 1 (cv): zero-state recurrence, 2 rows/thread packed f32x2.
// u tile staged TRANSPOSED in smem: su[t][b], pad 130 (even -> LDS.64 ok).
// ---------------------------------------------------------------------------
__global__ void __launch_bounds__(BT) cv_kernel(const float* __restrict__ u,
                                                const float* __restrict__ W) {
    __shared__ __align__(16) float su[71][BT + 2];   // [cc][r]
    int m  = blockIdx.x >> 5;
    int b0 = (blockIdx.x & 31) * BT;
    int tid = threadIdx.x;
    int lane = tid & 31, wr = tid >> 5;

    // coalesced load, transposed store (banks (2cc+r)%32: 2-way, load phase only)
    #pragma unroll
    for (int r = wr; r < BT; r += 4) {
        const float* ur = u + (size_t)(b0 + r) * SU + 1 + m * KC;
        #pragma unroll
        for (int ci = 0; ci < 3; ci++) {
            int cc = lane + ci * 32;
            if (cc < 71) su[cc][r] = ur[cc];
        }
    }
    __syncthreads();

    if (tid < BT / 2) {
        u64 a2[ORD], wu2[EX];
        load_coefs_packed(W, a2, wu2);

        u64 w[ORD], uw[ORD];
        u64 z = pk2(0.0f, 0.0f);
        #pragma unroll
        for (int k = 0; k < ORD; k++) {
            w[k]  = z;
            uw[k] = *(const u64*)&su[k][2 * tid];
        }

        #pragma unroll
        for (int j = 0; j < KC; j++) {
            u64 x = step_packed(a2, wu2, uw, w, j);
            if (j + 9 <= 70) uw[j % 9] = *(const u64*)&su[j + 9][2 * tid];
            w[j % 9] = x;
        }

        #pragma unroll
        for (int k = 0; k < ORD; k++)
            *(u64*)&g_v[((size_t)m * ORD + k) * BB + b0 + 2 * tid] = w[(k + KC) % 9];
    }
}

// ---------------------------------------------------------------------------
// Kernel 2 (states): M = A^K in registers via lane recurrences + shfl;
// 31-step boundary chain with 2-deep v prefetch. out[b][0..8] = y.
// ---------------------------------------------------------------------------
__global__ void __launch_bounds__(32) states_kernel(const float* __restrict__ W,
                                                    const float* __restrict__ y,
                                                    float* __restrict__ out) {
    int lane = threadIdx.x;
    int b = blockIdx.x * 32 + lane;

    float a[ORD];
    load_a(W, a);

    float w[ORD];
    #pragma unroll
    for (int k = 0; k < ORD; k++) w[k] = (k == lane) ? 1.0f : 0.0f;
    #pragma unroll
    for (int p = 0; p < KC; p++) {
        float z = 0.0f;
        #pragma unroll
        for (int k = 0; k < ORD; k++) z += a[k] * w[(k + p) % 9];
        w[p % 9] = z;
    }
    float MT[ORD * ORD];
    #pragma unroll
    for (int r = 0; r < ORD; r++)
        #pragma unroll
        for (int k = 0; k < ORD; k++)
            MT[r * ORD + k] = __shfl_sync(0xffffffffu, w[(k + KC) % 9], r);

    float s[ORD];
    #pragma unroll
    for (int k = 0; k < ORD; k++) {
        s[k] = y[(size_t)b * ORD + k];
        out[(size_t)b * OUTW + k] = s[k];
        g_s[(size_t)k * BB + b] = s[k];
    }

    float va[ORD], vb[ORD];
    #pragma unroll
    for (int k = 0; k < ORD; k++) va[k] = g_v[(size_t)k * BB + b];
    #pragma unroll
    for (int k = 0; k < ORD; k++) vb[k] = g_v[((size_t)ORD + k) * BB + b];

    #pragma unroll
    for (int m = 0; m < NCH - 1; m++) {
        float ns[ORD];
        #pragma unroll
        for (int k = 0; k < ORD; k++) ns[k] = va[k];
        #pragma unroll
        for (int k = 0; k < ORD; k++) va[k] = vb[k];
        if (m + 2 <= NCH - 2) {
            const float* gv = g_v + ((size_t)(m + 2) * ORD) * BB + b;
            #pragma unroll
            for (int k = 0; k < ORD; k++) vb[k] = gv[(size_t)k * BB];
        }
        #pragma unroll
        for (int r = 0; r < ORD; r++) {
            float sr = s[r];
            #pragma unroll
            for (int k = 0; k < ORD; k++) ns[k] += MT[r * ORD + k] * sr;
        }
        float* gs = g_s + ((size_t)(m + 1) * ORD) * BB + b;
        #pragma unroll
        for (int k = 0; k < ORD; k++) { s[k] = ns[k]; gs[(size_t)k * BB] = s[k]; }
    }
}

// ---------------------------------------------------------------------------
// Kernel 3 (pass2): true-state replay, 2 rows/thread packed; stage 16 steps
// in smem (STS.64), flush with all 128 threads in coalesced 64B segments.
// ---------------------------------------------------------------------------
__global__ void __launch_bounds__(BT) pass2_kernel(const float* __restrict__ u,
                                                   const float* __restrict__ W,
                                                   float* __restrict__ out) {
    __shared__ __align__(16) float su[71][BT + 2];
    __shared__ __align__(16) float sb[16][BT + 2];
    int m  = blockIdx.x >> 5;
    int b0 = (blockIdx.x & 31) * BT;
    int tid = threadIdx.x;
    int lane = tid & 31, wr = tid >> 5;

    #pragma unroll
    for (int r = wr; r < BT; r += 4) {
        const float* ur = u + (size_t)(b0 + r) * SU + 1 + m * KC;
        #pragma unroll
        for (int ci = 0; ci < 3; ci++) {
            int cc = lane + ci * 32;
            if (cc < 71) su[cc][r] = ur[cc];
        }
    }
    __syncthreads();

    u64 a2[ORD], wu2[EX];
    u64 w[ORD], uw[ORD];
    if (tid < BT / 2) {
        load_coefs_packed(W, a2, wu2);
        #pragma unroll
        for (int k = 0; k < ORD; k++) {
            w[k]  = *(const u64*)&g_s[((size_t)m * ORD + k) * BB + b0 + 2 * tid];
            uw[k] = *(const u64*)&su[k][2 * tid];
        }
    }

    int ocol0 = ORD + m * KC;

    #pragma unroll
    for (int j = 0; j < KC; j++) {
        if (tid < BT / 2) {
            u64 x = step_packed(a2, wu2, uw, w, j);
            if (j + 9 <= 70) uw[j % 9] = *(const u64*)&su[j + 9][2 * tid];
            w[j % 9] = x;
            *(u64*)&sb[j & 15][2 * tid] = x;
        }
        if ((j & 15) == 15) {
            __syncthreads();
            int jj = j & ~15;
            #pragma unroll
            for (int q = 0; q < 16; q++) {
                int e  = q * BT + tid;
                int tp = e & 15;
                int bp = e >> 4;
                out[(size_t)(b0 + bp) * OUTW + ocol0 + jj + tp] = sb[tp][bp];
            }
            __syncthreads();
        }
    }
}

// ---------------------------------------------------------------------------
extern "C" void kernel_launch(void* const* d_in, const int* in_sizes, int n_in,
                              void* d_out, int out_size) {
    const float* y = (const float*)d_in[0];
    const float* u = (const float*)d_in[1];
    const float* W = (const float*)d_in[2];
    for (int i = 0; i < n_in; i++) {
        if (in_sizes[i] == BB * ORD)      y = (const float*)d_in[i];
        else if (in_sizes[i] == BB * SU)  u = (const float*)d_in[i];
        else if (in_sizes[i] == 16)       W = (const float*)d_in[i];
    }
    float* out = (float*)d_out;

    cv_kernel<<<NCH * (BB / BT), BT>>>(u, W);       // 1024 x 128
    states_kernel<<<BB / 32, 32>>>(W, y, out);      // 128 x 32
    pass2_kernel<<<NCH * (BB / BT), BT>>>(u, W, out);
}

// round 7
// speedup vs baseline: 1.1058x; 1.1058x over previous
#include <cuda_runtime.h>
#include <cuda_bf16.h>

#define BB   4096      // batch rows
#define SEQ  2048      // sequence length S
#define SU   2056      // u row stride (S + E)
#define OUTW 2057      // out row stride (S + AR + 1)
#define KC   64        // chunk length
#define NCH  32        // chunks per row (SEQ / KC)
#define ORD  9         // recurrence order (AR + 1)
#define EX   8         // exogenous dim
#define BT   128       // b-rows per block in the two big passes

// Static device scratch (b-fastest layouts, coalesced for lane = b)
__device__ float g_v[NCH * ORD * BB];      // [m][k][b] zero-state final windows
__device__ float g_s[NCH * ORD * BB];      // [m][k][b] true boundary states

__device__ __forceinline__ void load_a(const float* __restrict__ W, float* a) {
    a[0] = -__ldg(&W[0]);
    #pragma unroll
    for (int k = 1; k < 8; k++) a[k] = __ldg(&W[k - 1]) - __ldg(&W[k]);
    a[8] = 1.0f + __ldg(&W[7]);
}

// One scalar recurrence step (17 FMA-class ops), compile-time rotation.
// Consumes u cols j..j+7 from uw (logical slots (e+j)%9), state from w.
__device__ __forceinline__ float step_rec(const float* a, const float* wu,
                                          const float* uw, const float* w, int j) {
    float e0 = wu[0] * uw[(0 + j) % 9] + wu[1] * uw[(1 + j) % 9];
    float e1 = wu[2] * uw[(2 + j) % 9] + wu[3] * uw[(3 + j) % 9];
    float e2 = wu[4] * uw[(4 + j) % 9] + wu[5] * uw[(5 + j) % 9];
    float e3 = wu[6] * uw[(6 + j) % 9] + wu[7] * uw[(7 + j) % 9];
    float c  = (e0 + e1) + (e2 + e3);
    float s0 = c + a[0] * w[(0 + j) % 9];
    float s1 = a[1] * w[(1 + j) % 9] + a[2] * w[(2 + j) % 9];
    float s2 = a[3] * w[(3 + j) % 9] + a[4] * w[(4 + j) % 9];
    float s3 = a[5] * w[(5 + j) % 9] + a[6] * w[(6 + j) % 9];
    float x  = ((s0 + s1) + (s2 + s3)) + a[7] * w[(7 + j) % 9];
    return fmaf(a[8], w[(8 + j) % 9], x);
}

// Cooperative phased tile load: cols [c0, c0+38] of this block's 128 u-rows
// into su[r][0..38]. Coalesced LDG along rows.
__device__ __forceinline__ void load_utile(const float* __restrict__ u,
                                           float su[BT][41],
                                           int b0, int m, int c0,
                                           int lane, int wr) {
    #pragma unroll
    for (int r = wr; r < BT; r += 4) {
        const float* ur = u + (size_t)(b0 + r) * SU + 1 + m * KC + c0;
        su[r][lane] = ur[lane];
        if (lane < 7) su[r][lane + 32] = ur[lane + 32];
    }
}

// ---------------------------------------------------------------------------
// Kernel 1 (cv): zero-state recurrence per (chunk m, row b); 64 steps in two
// 32-step phases so the u tile is only 39 cols (21 KB smem -> ~2x occupancy).
// Emits only the final 9-window to g_v[m][k][b].
// ---------------------------------------------------------------------------
__global__ void __launch_bounds__(BT) cv_kernel(const float* __restrict__ u,
                                                const float* __restrict__ W) {
    __shared__ float su[BT][41];           // stride 41: gcd(41,32)=1, conflict-free
    int m  = blockIdx.x >> 5;
    int b0 = (blockIdx.x & 31) * BT;
    int tid = threadIdx.x;
    int lane = tid & 31, wr = tid >> 5;

    float a[ORD], wu[EX];
    load_a(W, a);
    #pragma unroll
    for (int e = 0; e < EX; e++) wu[e] = __ldg(&W[8 + e]);

    // Phase A: cols 0..38
    load_utile(u, su, b0, m, 0, lane, wr);
    __syncthreads();

    float w[ORD], uw[ORD];
    #pragma unroll
    for (int k = 0; k < ORD; k++) { w[k] = 0.0f; uw[k] = su[tid][k]; }

    #pragma unroll
    for (int j = 0; j < 32; j++) {
        float x = step_rec(a, wu, uw, w, j);
        if (j <= 29) uw[j % 9] = su[tid][j + 9];   // cols 9..38
        w[j % 9] = x;
    }
    __syncthreads();

    // Phase B: cols 32..70 at su[tid][cc-32]
    load_utile(u, su, b0, m, 32, lane, wr);
    __syncthreads();
    uw[30 % 9] = su[tid][7];   // col 39 (deferred refill of step 30)
    uw[31 % 9] = su[tid][8];   // col 40 (deferred refill of step 31)

    #pragma unroll
    for (int j = 32; j < KC; j++) {
        float x = step_rec(a, wu, uw, w, j);
        if (j <= 61) uw[j % 9] = su[tid][j - 23];  // col j+9
        w[j % 9] = x;
    }

    float* gv = g_v + ((size_t)m * ORD) * BB + b0 + tid;
    #pragma unroll
    for (int k = 0; k < ORD; k++) gv[(size_t)k * BB] = w[(k + KC) % 9];
}

// ---------------------------------------------------------------------------
// Kernel 2 (states): M = A^K in registers via lane recurrences + shfl;
// 31-step boundary chain with 2-deep v prefetch. out[b][0..8] = y.
// ---------------------------------------------------------------------------
__global__ void __launch_bounds__(32) states_kernel(const float* __restrict__ W,
                                                    const float* __restrict__ y,
                                                    float* __restrict__ out) {
    int lane = threadIdx.x;
    int b = blockIdx.x * 32 + lane;

    float a[ORD];
    load_a(W, a);

    float w[ORD];
    #pragma unroll
    for (int k = 0; k < ORD; k++) w[k] = (k == lane) ? 1.0f : 0.0f;
    #pragma unroll
    for (int p = 0; p < KC; p++) {
        float z = 0.0f;
        #pragma unroll
        for (int k = 0; k < ORD; k++) z += a[k] * w[(k + p) % 9];
        w[p % 9] = z;
    }
    float MT[ORD * ORD];
    #pragma unroll
    for (int r = 0; r < ORD; r++)
        #pragma unroll
        for (int k = 0; k < ORD; k++)
            MT[r * ORD + k] = __shfl_sync(0xffffffffu, w[(k + KC) % 9], r);

    float s[ORD];
    #pragma unroll
    for (int k = 0; k < ORD; k++) {
        s[k] = y[(size_t)b * ORD + k];
        out[(size_t)b * OUTW + k] = s[k];
        g_s[(size_t)k * BB + b] = s[k];
    }

    float va[ORD], vb[ORD];
    #pragma unroll
    for (int k = 0; k < ORD; k++) va[k] = g_v[(size_t)k * BB + b];
    #pragma unroll
    for (int k = 0; k < ORD; k++) vb[k] = g_v[((size_t)ORD + k) * BB + b];

    #pragma unroll
    for (int m = 0; m < NCH - 1; m++) {
        float ns[ORD];
        #pragma unroll
        for (int k = 0; k < ORD; k++) ns[k] = va[k];
        #pragma unroll
        for (int k = 0; k < ORD; k++) va[k] = vb[k];
        if (m + 2 <= NCH - 2) {
            const float* gv = g_v + ((size_t)(m + 2) * ORD) * BB + b;
            #pragma unroll
            for (int k = 0; k < ORD; k++) vb[k] = gv[(size_t)k * BB];
        }
        #pragma unroll
        for (int r = 0; r < ORD; r++) {
            float sr = s[r];
            #pragma unroll
            for (int k = 0; k < ORD; k++) ns[k] += MT[r * ORD + k] * sr;
        }
        float* gs = g_s + ((size_t)(m + 1) * ORD) * BB + b;
        #pragma unroll
        for (int k = 0; k < ORD; k++) { s[k] = ns[k]; gs[(size_t)k * BB] = s[k]; }
    }
}

// ---------------------------------------------------------------------------
// Kernel 3 (pass2): true-state replay, same two-phase u tile; stages 16 steps
// in smem and flushes to out in coalesced 64B row segments.
// ---------------------------------------------------------------------------
__global__ void __launch_bounds__(BT) pass2_kernel(const float* __restrict__ u,
                                                   const float* __restrict__ W,
                                                   float* __restrict__ out) {
    __shared__ float su[BT][41];
    __shared__ float sb[16][BT + 1];
    int m  = blockIdx.x >> 5;
    int b0 = (blockIdx.x & 31) * BT;
    int tid = threadIdx.x;
    int lane = tid & 31, wr = tid >> 5;
    int ocol0 = ORD + m * KC;

    float a[ORD], wu[EX];
    load_a(W, a);
    #pragma unroll
    for (int e = 0; e < EX; e++) wu[e] = __ldg(&W[8 + e]);

    load_utile(u, su, b0, m, 0, lane, wr);
    __syncthreads();

    float w[ORD], uw[ORD];
    const float* gs = g_s + ((size_t)m * ORD) * BB + b0 + tid;
    #pragma unroll
    for (int k = 0; k < ORD; k++) { w[k] = gs[(size_t)k * BB]; uw[k] = su[tid][k]; }

    #pragma unroll
    for (int j = 0; j < 32; j++) {
        float x = step_rec(a, wu, uw, w, j);
        if (j <= 29) uw[j % 9] = su[tid][j + 9];
        w[j % 9] = x;
        sb[j & 15][tid] = x;
        if ((j & 15) == 15) {
            __syncthreads();
            int jj = j & ~15;
            #pragma unroll
            for (int q = 0; q < 16; q++) {
                int e  = q * BT + tid;
                int tp = e & 15;
                int bp = e >> 4;
                out[(size_t)(b0 + bp) * OUTW + ocol0 + jj + tp] = sb[tp][bp];
            }
            __syncthreads();
        }
    }

    load_utile(u, su, b0, m, 32, lane, wr);
    __syncthreads();
    uw[30 % 9] = su[tid][7];   // col 39
    uw[31 % 9] = su[tid][8];   // col 40

    #pragma unroll
    for (int j = 32; j < KC; j++) {
        float x = step_rec(a, wu, uw, w, j);
        if (j <= 61) uw[j % 9] = su[tid][j - 23];
        w[j % 9] = x;
        sb[j & 15][tid] = x;
        if ((j & 15) == 15) {
            __syncthreads();
            int jj = j & ~15;
            #pragma unroll
            for (int q = 0; q < 16; q++) {
                int e  = q * BT + tid;
                int tp = e & 15;
                int bp = e >> 4;
                out[(size_t)(b0 + bp) * OUTW + ocol0 + jj + tp] = sb[tp][bp];
            }
            __syncthreads();
        }
    }
}

// ---------------------------------------------------------------------------
extern "C" void kernel_launch(void* const* d_in, const int* in_sizes, int n_in,
                              void* d_out, int out_size) {
    const float* y = (const float*)d_in[0];
    const float* u = (const float*)d_in[1];
    const float* W = (const float*)d_in[2];
    for (int i = 0; i < n_in; i++) {
        if (in_sizes[i] == BB * ORD)      y = (const float*)d_in[i];
        else if (in_sizes[i] == BB * SU)  u = (const float*)d_in[i];
        else if (in_sizes[i] == 16)       W = (const float*)d_in[i];
    }
    float* out = (float*)d_out;

    // Max shared-memory carveout so resident blocks are reg-limited, not
    // carveout-limited (idempotent host calls; not stream ops).
    static int carveout_done = 0;
    (void)carveout_done;
    cudaFuncSetAttribute(cv_kernel,    cudaFuncAttributePreferredSharedMemoryCarveout, 100);
    cudaFuncSetAttribute(pass2_kernel, cudaFuncAttributePreferredSharedMemoryCarveout, 100);

    cv_kernel<<<NCH * (BB / BT), BT>>>(u, W);       // 1024 x 128
    states_kernel<<<BB / 32, 32>>>(W, y, out);      // 128 x 32
    pass2_kernel<<<NCH * (BB / BT), BT>>>(u, W, out);
}